// round 15
// baseline (speedup 1.0000x reference)
#include <cuda_runtime.h>
#include <cuda_bf16.h>
#include <math.h>
#include <stdint.h>

#define BATCH 256
#define SEQ   512
#define DIN   64
#define HID   256
#define MROWS (BATCH * SEQ)       // 131072

__device__ float g_bufA[(size_t)MROWS * HID];
__device__ float g_hfin[(size_t)BATCH * HID];
__device__ __nv_bfloat16 g_xhi[(size_t)MROWS * DIN];
__device__ __nv_bfloat16 g_xlo[(size_t)MROWS * DIN];
__device__ __nv_bfloat16 g_hhi[(size_t)MROWS * HID];
__device__ __nv_bfloat16 g_whi[HID * HID];
__device__ __nv_bfloat16 g_wlo[HID * HID];

// ---------------------------------------------------------------------------
// helpers
// ---------------------------------------------------------------------------
__device__ __forceinline__ float tanh_fast(float x) {
    float r;
    asm("tanh.approx.f32 %0, %1;" : "=f"(r) : "f"(x));
    return r;
}
__device__ __forceinline__ uint32_t f2bf2(float a, float b) {
    uint32_t r;
    asm("cvt.rn.bf16x2.f32 %0, %2, %1;" : "=r"(r) : "f"(a), "f"(b));
    return r;
}
__device__ __forceinline__ void mma16816(float* c, const uint32_t* a,
                                         uint32_t b0, uint32_t b1) {
    asm volatile(
        "mma.sync.aligned.m16n8k16.row.col.f32.bf16.bf16.f32 "
        "{%0,%1,%2,%3}, {%4,%5,%6,%7}, {%8,%9}, {%0,%1,%2,%3};"
        : "+f"(c[0]), "+f"(c[1]), "+f"(c[2]), "+f"(c[3])
        : "r"(a[0]), "r"(a[1]), "r"(a[2]), "r"(a[3]), "r"(b0), "r"(b1));
}
__device__ __forceinline__ void cp16(uint32_t dst, const void* src) {
    asm volatile("cp.async.ca.shared.global [%0], [%1], 16;"
                 :: "r"(dst), "l"(src));
}
#define CP_COMMIT() asm volatile("cp.async.commit_group;" ::: "memory")
#define CP_WAIT(n)  asm volatile("cp.async.wait_group %0;" :: "n"(n) : "memory")

// ---------------------------------------------------------------------------
// f32 -> (bf16 hi, bf16 lo) split conversion
// ---------------------------------------------------------------------------
__global__ void cvt_split_kernel(const float* __restrict__ in,
                                 __nv_bfloat16* __restrict__ hi,
                                 __nv_bfloat16* __restrict__ lo, int n4) {
    __nv_bfloat162* h2 = reinterpret_cast<__nv_bfloat162*>(hi);
    __nv_bfloat162* l2 = reinterpret_cast<__nv_bfloat162*>(lo);
    const float4* in4 = reinterpret_cast<const float4*>(in);
    for (int i = blockIdx.x * blockDim.x + threadIdx.x; i < n4;
         i += gridDim.x * blockDim.x) {
        float4 v = in4[i];
        __nv_bfloat16 a = __float2bfloat16(v.x), b = __float2bfloat16(v.y);
        __nv_bfloat16 c = __float2bfloat16(v.z), d = __float2bfloat16(v.w);
        __nv_bfloat16 ra = __float2bfloat16(v.x - __bfloat162float(a));
        __nv_bfloat16 rb = __float2bfloat16(v.y - __bfloat162float(b));
        __nv_bfloat16 rc = __float2bfloat16(v.z - __bfloat162float(c));
        __nv_bfloat16 rd = __float2bfloat16(v.w - __bfloat162float(d));
        h2[2 * i]     = __nv_bfloat162{a, b};
        h2[2 * i + 1] = __nv_bfloat162{c, d};
        l2[2 * i]     = __nv_bfloat162{ra, rb};
        l2[2 * i + 1] = __nv_bfloat162{rc, rd};
    }
}

// ---------------------------------------------------------------------------
// Tensor-core RNN recurrence v2. 16 blocks x 512 threads (16 warps).
// Block owns 16 batch rows; warp w owns outputs n0..n0+15 (two n8 tiles).
// n-tile 0 weights: 32 B-fragment regs; n-tile 1 weights: smem (64 KB,
// lane-consecutive -> conflict-free). Register budget ~70 (no spills).
// h (bf16) double-buffered in smem, row stride 264 -> conflict-free frags.
// ---------------------------------------------------------------------------
#define H_STRIDE 264
#define WSM_WORDS (16 * 2 * 512)                         // 64 KB
#define RECUR_SMEM (WSM_WORDS * 4 + 2 * 16 * H_STRIDE * 2)

__global__ __launch_bounds__(512, 1) void rnn_recur_tc(
    const float* __restrict__ xp,        // [BATCH, SEQ, HID] f32, bias added
    const float* __restrict__ Whh,       // [HID, HID] f32
    __nv_bfloat16* __restrict__ out_hi,  // [BATCH, SEQ, HID] bf16 or null
    float* __restrict__ out_final)       // [BATCH, HID] f32 or null
{
    extern __shared__ char smraw[];
    uint32_t* wsm = reinterpret_cast<uint32_t*>(smraw);            // [16][2][512]
    __nv_bfloat16* hs0 = reinterpret_cast<__nv_bfloat16*>(smraw + WSM_WORDS * 4);
    __nv_bfloat16* hs1 = hs0 + 16 * H_STRIDE;

    const int t    = threadIdx.x;
    const int lane = t & 31;
    const int w    = t >> 5;             // 0..15
    const int row0 = blockIdx.x * 16;
    const int n0   = w * 16;

    // ---- n-tile 0 weights -> registers; n-tile 1 weights -> smem ----
    uint32_t bf0[16][2];
    {
        const int nr0 = n0 + (lane >> 2);
        const int nr1 = n0 + 8 + (lane >> 2);
        const float* wr0 = Whh + nr0 * HID;
        const float* wr1 = Whh + nr1 * HID;
#pragma unroll
        for (int ks = 0; ks < 16; ks++) {
            const int k = ks * 16 + (lane & 3) * 2;
            float2 p0 = *reinterpret_cast<const float2*>(wr0 + k);
            float2 p1 = *reinterpret_cast<const float2*>(wr0 + k + 8);
            bf0[ks][0] = f2bf2(p0.x, p0.y);
            bf0[ks][1] = f2bf2(p1.x, p1.y);
            float2 q0 = *reinterpret_cast<const float2*>(wr1 + k);
            float2 q1 = *reinterpret_cast<const float2*>(wr1 + k + 8);
            wsm[(ks * 2 + 0) * 512 + t] = f2bf2(q0.x, q0.y);
            wsm[(ks * 2 + 1) * 512 + t] = f2bf2(q1.x, q1.y);
        }
    }

    // zero initial h (both buffers)
    for (int i = t; i < 2 * 16 * H_STRIDE; i += 512)
        reinterpret_cast<unsigned short*>(hs0)[i] = 0;
    __syncthreads();

    const int r1 = lane >> 2;
    const int r2 = r1 + 8;
    const int cq = (lane & 3) * 2;

    const float* xpr1 = xp + (size_t)(row0 + r1) * SEQ * HID;
    const float* xpr2 = xp + (size_t)(row0 + r2) * SEQ * HID;

    float2 px[2][2];
#pragma unroll
    for (int nt = 0; nt < 2; nt++) {
        const int c = n0 + nt * 8 + cq;
        px[nt][0] = *reinterpret_cast<const float2*>(xpr1 + c);
        px[nt][1] = *reinterpret_cast<const float2*>(xpr2 + c);
    }

    int buf = 0;
    for (int s = 0; s < SEQ; s++) {
        float2 cur[2][2];
#pragma unroll
        for (int nt = 0; nt < 2; nt++) {
            cur[nt][0] = px[nt][0];
            cur[nt][1] = px[nt][1];
        }
        if (s + 1 < SEQ) {
#pragma unroll
            for (int nt = 0; nt < 2; nt++) {
                const int c = n0 + nt * 8 + cq;
                px[nt][0] = *reinterpret_cast<const float2*>(
                    xpr1 + (size_t)(s + 1) * HID + c);
                px[nt][1] = *reinterpret_cast<const float2*>(
                    xpr2 + (size_t)(s + 1) * HID + c);
            }
        }

        float acc[2][4] = {{0.f, 0.f, 0.f, 0.f}, {0.f, 0.f, 0.f, 0.f}};
        const __nv_bfloat16* hb = buf ? hs1 : hs0;
#pragma unroll
        for (int ks = 0; ks < 16; ks++) {
            const int idx = r1 * H_STRIDE + ks * 16 + cq;
            uint32_t a[4];
            a[0] = *reinterpret_cast<const uint32_t*>(&hb[idx]);
            a[1] = *reinterpret_cast<const uint32_t*>(&hb[idx + 8 * H_STRIDE]);
            a[2] = *reinterpret_cast<const uint32_t*>(&hb[idx + 8]);
            a[3] = *reinterpret_cast<const uint32_t*>(&hb[idx + 8 * H_STRIDE + 8]);
            mma16816(acc[0], a, bf0[ks][0], bf0[ks][1]);
            uint32_t b1_0 = wsm[(ks * 2 + 0) * 512 + t];
            uint32_t b1_1 = wsm[(ks * 2 + 1) * 512 + t];
            mma16816(acc[1], a, b1_0, b1_1);
        }

        __nv_bfloat16* hn = buf ? hs0 : hs1;
#pragma unroll
        for (int nt = 0; nt < 2; nt++) {
            const int c = n0 + nt * 8 + cq;
            float h0 = tanh_fast(acc[nt][0] + cur[nt][0].x);
            float h1 = tanh_fast(acc[nt][1] + cur[nt][0].y);
            float h2 = tanh_fast(acc[nt][2] + cur[nt][1].x);
            float h3 = tanh_fast(acc[nt][3] + cur[nt][1].y);
            uint32_t p01 = f2bf2(h0, h1);
            uint32_t p23 = f2bf2(h2, h3);
            *reinterpret_cast<uint32_t*>(&hn[r1 * H_STRIDE + c]) = p01;
            *reinterpret_cast<uint32_t*>(&hn[r2 * H_STRIDE + c]) = p23;
            if (out_hi) {
                *reinterpret_cast<uint32_t*>(
                    out_hi + ((size_t)(row0 + r1) * SEQ + s) * HID + c) = p01;
                *reinterpret_cast<uint32_t*>(
                    out_hi + ((size_t)(row0 + r2) * SEQ + s) * HID + c) = p23;
            }
            if (out_final && s == SEQ - 1) {
                out_final[(size_t)(row0 + r1) * HID + c]     = h0;
                out_final[(size_t)(row0 + r1) * HID + c + 1] = h1;
                out_final[(size_t)(row0 + r2) * HID + c]     = h2;
                out_final[(size_t)(row0 + r2) * HID + c + 1] = h3;
            }
        }
        __syncthreads();
        buf ^= 1;
    }
}

// ---------------------------------------------------------------------------
// Tensor-core GEMM (mma.sync): Y[M,256] = X[M,K] @ W[256,K]^T + bias
// cp.async double-buffered K-chunks of 64. USE_ALO: 3 passes else 2 passes.
// ---------------------------------------------------------------------------
#define GSTRIDE 72
#define TILE_B  (128 * GSTRIDE)
#define BUF_B   (4 * TILE_B)
#define GEMM_SMEM (2 * BUF_B * 2 + 128 * 4)

template <int K, bool USE_ALO>
__global__ __launch_bounds__(256) void gemm_mma(
    const __nv_bfloat16* __restrict__ Ahi, const __nv_bfloat16* __restrict__ Alo,
    const __nv_bfloat16* __restrict__ Bhi, const __nv_bfloat16* __restrict__ Blo,
    const float* __restrict__ ba, const float* __restrict__ bb,
    float* __restrict__ Y)
{
    constexpr int NC = K / 64;
    extern __shared__ char smraw[];
    __nv_bfloat16* base = reinterpret_cast<__nv_bfloat16*>(smraw);
    float* bias = reinterpret_cast<float*>(base + 2 * BUF_B);

    const int t      = threadIdx.x;
    const int lane   = t & 31;
    const int wid    = t >> 5;
    const int warp_m = wid >> 1;
    const int warp_n = wid & 1;
    const size_t m0  = (size_t)blockIdx.x * 128;
    const int    n0  = blockIdx.y * 128;

    if (t < 128) bias[t] = ba[n0 + t] + bb[n0 + t];

    float acc[2][8][4];
#pragma unroll
    for (int mt = 0; mt < 2; mt++)
#pragma unroll
        for (int nt = 0; nt < 8; nt++)
#pragma unroll
            for (int i = 0; i < 4; i++) acc[mt][nt][i] = 0.0f;

    const int srow  = t >> 1;
    const int shalf = t & 1;

    const __nv_bfloat16* gA[2] = {Ahi + (m0 + srow) * K + shalf * 32,
                                  Alo + (m0 + srow) * K + shalf * 32};
    const __nv_bfloat16* gB[2] = {Bhi + (size_t)(n0 + srow) * K + shalf * 32,
                                  Blo + (size_t)(n0 + srow) * K + shalf * 32};
    const uint32_t dbase =
        (uint32_t)__cvta_generic_to_shared(base) +
        (uint32_t)((srow * GSTRIDE + shalf * 32) * 2);

    auto issue_chunk = [&](int ci) {
        const uint32_t db = dbase + (uint32_t)((ci & 1) * BUF_B * 2);
        const int koff = ci * 64;
#pragma unroll
        for (int q = 0; q < 4; q++) {
            cp16(db + 0 * TILE_B * 2 + q * 16, gA[0] + koff + q * 8);
            if constexpr (USE_ALO)
                cp16(db + 1 * TILE_B * 2 + q * 16, gA[1] + koff + q * 8);
            cp16(db + 2 * TILE_B * 2 + q * 16, gB[0] + koff + q * 8);
            cp16(db + 3 * TILE_B * 2 + q * 16, gB[1] + koff + q * 8);
        }
        CP_COMMIT();
    };

    issue_chunk(0);
    if (NC > 1) issue_chunk(1);

    for (int ci = 0; ci < NC; ci++) {
        if (ci + 1 < NC) CP_WAIT(1); else CP_WAIT(0);
        __syncthreads();

        const __nv_bfloat16* Ahs = base + (ci & 1) * BUF_B;
        const __nv_bfloat16* Als = Ahs + TILE_B;
        const __nv_bfloat16* Bhs = Als + TILE_B;
        const __nv_bfloat16* Bls = Bhs + TILE_B;

#pragma unroll
        for (int ks = 0; ks < 4; ks++) {
            const int k0 = ks * 16;
            uint32_t ah[2][4], al[2][4];
#pragma unroll
            for (int mt = 0; mt < 2; mt++) {
                int idx = (warp_m * 32 + mt * 16 + (lane >> 2)) * GSTRIDE +
                          k0 + (lane & 3) * 2;
                ah[mt][0] = *reinterpret_cast<const uint32_t*>(&Ahs[idx]);
                ah[mt][1] = *reinterpret_cast<const uint32_t*>(&Ahs[idx + 8 * GSTRIDE]);
                ah[mt][2] = *reinterpret_cast<const uint32_t*>(&Ahs[idx + 8]);
                ah[mt][3] = *reinterpret_cast<const uint32_t*>(&Ahs[idx + 8 * GSTRIDE + 8]);
                if constexpr (USE_ALO) {
                    al[mt][0] = *reinterpret_cast<const uint32_t*>(&Als[idx]);
                    al[mt][1] = *reinterpret_cast<const uint32_t*>(&Als[idx + 8 * GSTRIDE]);
                    al[mt][2] = *reinterpret_cast<const uint32_t*>(&Als[idx + 8]);
                    al[mt][3] = *reinterpret_cast<const uint32_t*>(&Als[idx + 8 * GSTRIDE + 8]);
                }
            }
#pragma unroll
            for (int nt = 0; nt < 8; nt++) {
                int idxb = (warp_n * 64 + nt * 8 + (lane >> 2)) * GSTRIDE +
                           k0 + (lane & 3) * 2;
                uint32_t bh0 = *reinterpret_cast<const uint32_t*>(&Bhs[idxb]);
                uint32_t bh1 = *reinterpret_cast<const uint32_t*>(&Bhs[idxb + 8]);
                uint32_t bl0 = *reinterpret_cast<const uint32_t*>(&Bls[idxb]);
                uint32_t bl1 = *reinterpret_cast<const uint32_t*>(&Bls[idxb + 8]);
#pragma unroll
                for (int mt = 0; mt < 2; mt++) {
                    mma16816(acc[mt][nt], ah[mt], bh0, bh1);
                    mma16816(acc[mt][nt], ah[mt], bl0, bl1);
                    if constexpr (USE_ALO)
                        mma16816(acc[mt][nt], al[mt], bh0, bh1);
                }
            }
        }
        __syncthreads();
        if (ci + 2 < NC) issue_chunk(ci + 2);
    }

#pragma unroll
    for (int mt = 0; mt < 2; mt++) {
        const size_t rbase = m0 + warp_m * 32 + mt * 16 + (lane >> 2);
#pragma unroll
        for (int nt = 0; nt < 8; nt++) {
            const int cl = warp_n * 64 + nt * 8 + (lane & 3) * 2;
            float b0 = bias[cl], b1 = bias[cl + 1];
            float2 v0 = make_float2(acc[mt][nt][0] + b0, acc[mt][nt][1] + b1);
            float2 v1 = make_float2(acc[mt][nt][2] + b0, acc[mt][nt][3] + b1);
            *reinterpret_cast<float2*>(Y + rbase * HID + n0 + cl) = v0;
            *reinterpret_cast<float2*>(Y + (rbase + 8) * HID + n0 + cl) = v1;
        }
    }
}

// ---------------------------------------------------------------------------
// out[b] = sigmoid(h2[b,:] . Wfc + bfc)
// ---------------------------------------------------------------------------
__global__ void fc_sigmoid_kernel(const float* __restrict__ h2,
                                  const float* __restrict__ Wfc,
                                  const float* __restrict__ bfc,
                                  float* __restrict__ out)
{
    __shared__ float wf[HID];
    const int t = threadIdx.x;
    wf[t] = Wfc[t];
    __syncthreads();
    const float* hb = h2 + (size_t)t * HID;
    float s = 0.0f;
#pragma unroll 8
    for (int k = 0; k < HID; k++) s = fmaf(hb[k], wf[k], s);
    float z = s + bfc[0];
    out[t] = 1.0f / (1.0f + expf(-z));
}

// ---------------------------------------------------------------------------
// launch
// ---------------------------------------------------------------------------
extern "C" void kernel_launch(void* const* d_in, const int* in_sizes, int n_in,
                              void* d_out, int out_size)
{
    const float* x     = (const float*)d_in[0];
    const float* W_ih0 = (const float*)d_in[1];
    const float* W_hh0 = (const float*)d_in[2];
    const float* b_ih0 = (const float*)d_in[3];
    const float* b_hh0 = (const float*)d_in[4];
    const float* W_ih1 = (const float*)d_in[5];
    const float* W_hh1 = (const float*)d_in[6];
    const float* b_ih1 = (const float*)d_in[7];
    const float* b_hh1 = (const float*)d_in[8];
    const float* W_fc  = (const float*)d_in[9];
    const float* b_fc  = (const float*)d_in[10];
    float* out = (float*)d_out;

    float *bufA, *hfin;
    __nv_bfloat16 *xhi, *xlo, *hhi, *whi, *wlo;
    cudaGetSymbolAddress((void**)&bufA, g_bufA);
    cudaGetSymbolAddress((void**)&hfin, g_hfin);
    cudaGetSymbolAddress((void**)&xhi, g_xhi);
    cudaGetSymbolAddress((void**)&xlo, g_xlo);
    cudaGetSymbolAddress((void**)&hhi, g_hhi);
    cudaGetSymbolAddress((void**)&whi, g_whi);
    cudaGetSymbolAddress((void**)&wlo, g_wlo);

    cudaFuncSetAttribute(gemm_mma<DIN, true>,
                         cudaFuncAttributeMaxDynamicSharedMemorySize, GEMM_SMEM);
    cudaFuncSetAttribute(gemm_mma<HID, false>,
                         cudaFuncAttributeMaxDynamicSharedMemorySize, GEMM_SMEM);
    cudaFuncSetAttribute(rnn_recur_tc,
                         cudaFuncAttributeMaxDynamicSharedMemorySize, RECUR_SMEM);

    const dim3 ggrid(MROWS / 128, 2);

    // ---- phase A: xp0 = x @ W_ih0^T + (b_ih0+b_hh0), bf16x3 ----
    cvt_split_kernel<<<1024, 256>>>(x, xhi, xlo, MROWS * DIN / 4);
    cvt_split_kernel<<<64, 256>>>(W_ih0, whi, wlo, HID * DIN / 4);
    gemm_mma<DIN, true><<<ggrid, 256, GEMM_SMEM>>>(xhi, xlo, whi, wlo,
                                                   b_ih0, b_hh0, bufA);
    // ---- phase B: layer-0 recurrence (tensor cores), emits bf16 h1 ----
    rnn_recur_tc<<<BATCH / 16, 512, RECUR_SMEM>>>(bufA, W_hh0, hhi, (float*)0);
    // ---- phase C: xp1 = h1 @ W_ih1^T + (b_ih1+b_hh1), 2-pass ----
    cvt_split_kernel<<<64, 256>>>(W_ih1, whi, wlo, HID * HID / 4);
    gemm_mma<HID, false><<<ggrid, 256, GEMM_SMEM>>>(hhi, hhi, whi, wlo,
                                                    b_ih1, b_hh1, bufA);
    // ---- phase D: layer-1 recurrence (tensor cores) -> final h ----
    rnn_recur_tc<<<BATCH / 16, 512, RECUR_SMEM>>>(bufA, W_hh1,
                                                  (__nv_bfloat16*)0, hfin);
    // ---- phase E: fc + sigmoid ----
    fc_sigmoid_kernel<<<1, HID>>>(hfin, W_fc, b_fc, out);
}

// round 17
// speedup vs baseline: 1.5953x; 1.5953x over previous
#include <cuda_runtime.h>
#include <cuda_bf16.h>
#include <math.h>
#include <stdint.h>

#define BATCH 256
#define SEQ   512
#define DIN   64
#define HID   256
#define MROWS (BATCH * SEQ)       // 131072

__device__ float g_bufA[(size_t)MROWS * HID];
__device__ float g_hfin[(size_t)BATCH * HID];
__device__ __nv_bfloat16 g_xhi[(size_t)MROWS * DIN];
__device__ __nv_bfloat16 g_xlo[(size_t)MROWS * DIN];
__device__ __nv_bfloat16 g_hhi[(size_t)MROWS * HID];
__device__ __nv_bfloat16 g_whi[HID * HID];
__device__ __nv_bfloat16 g_wlo[HID * HID];

// ---------------------------------------------------------------------------
// helpers
// ---------------------------------------------------------------------------
__device__ __forceinline__ unsigned long long ffma2(unsigned long long a,
                                                    unsigned long long b,
                                                    unsigned long long c) {
    unsigned long long d;
    asm("fma.rn.f32x2 %0, %1, %2, %3;" : "=l"(d) : "l"(a), "l"(b), "l"(c));
    return d;
}
__device__ __forceinline__ float2 u2f(unsigned long long v) {
    float2 r;
    asm("mov.b64 {%0, %1}, %2;" : "=f"(r.x), "=f"(r.y) : "l"(v));
    return r;
}
__device__ __forceinline__ float tanh_fast(float x) {
    float r;
    asm("tanh.approx.f32 %0, %1;" : "=f"(r) : "f"(x));
    return r;
}
__device__ __forceinline__ void mma16816(float* c, const uint32_t* a,
                                         uint32_t b0, uint32_t b1) {
    asm volatile(
        "mma.sync.aligned.m16n8k16.row.col.f32.bf16.bf16.f32 "
        "{%0,%1,%2,%3}, {%4,%5,%6,%7}, {%8,%9}, {%0,%1,%2,%3};"
        : "+f"(c[0]), "+f"(c[1]), "+f"(c[2]), "+f"(c[3])
        : "r"(a[0]), "r"(a[1]), "r"(a[2]), "r"(a[3]), "r"(b0), "r"(b1));
}
__device__ __forceinline__ void cp16(uint32_t dst, const void* src) {
    asm volatile("cp.async.ca.shared.global [%0], [%1], 16;"
                 :: "r"(dst), "l"(src));
}
#define CP_COMMIT() asm volatile("cp.async.commit_group;" ::: "memory")
#define CP_WAIT(n)  asm volatile("cp.async.wait_group %0;" :: "n"(n) : "memory")

// ---------------------------------------------------------------------------
// f32 -> (bf16 hi, bf16 lo) split conversion
// ---------------------------------------------------------------------------
__global__ void cvt_split_kernel(const float* __restrict__ in,
                                 __nv_bfloat16* __restrict__ hi,
                                 __nv_bfloat16* __restrict__ lo, int n4) {
    __nv_bfloat162* h2 = reinterpret_cast<__nv_bfloat162*>(hi);
    __nv_bfloat162* l2 = reinterpret_cast<__nv_bfloat162*>(lo);
    const float4* in4 = reinterpret_cast<const float4*>(in);
    for (int i = blockIdx.x * blockDim.x + threadIdx.x; i < n4;
         i += gridDim.x * blockDim.x) {
        float4 v = in4[i];
        __nv_bfloat16 a = __float2bfloat16(v.x), b = __float2bfloat16(v.y);
        __nv_bfloat16 c = __float2bfloat16(v.z), d = __float2bfloat16(v.w);
        __nv_bfloat16 ra = __float2bfloat16(v.x - __bfloat162float(a));
        __nv_bfloat16 rb = __float2bfloat16(v.y - __bfloat162float(b));
        __nv_bfloat16 rc = __float2bfloat16(v.z - __bfloat162float(c));
        __nv_bfloat16 rd = __float2bfloat16(v.w - __bfloat162float(d));
        h2[2 * i]     = __nv_bfloat162{a, b};
        h2[2 * i + 1] = __nv_bfloat162{c, d};
        l2[2 * i]     = __nv_bfloat162{ra, rb};
        l2[2 * i + 1] = __nv_bfloat162{rc, rd};
    }
}

// ---------------------------------------------------------------------------
// Recurrence — champion FFMA structure (736 us/layer). Only delta vs R12:
// out_seq is emitted as bf16 (hi only): one CVT (idle ALU pipe) + STG.16
// replaces STG.32. The recurrent state itself stays full fp32.
// ---------------------------------------------------------------------------
__global__ __launch_bounds__(512, 1) void rnn_recur_kernel(
    const float* __restrict__ xp, const float* __restrict__ Whh,
    __nv_bfloat16* __restrict__ out_seq,   // bf16 hi or null
    float* __restrict__ out_final)
{
    __shared__ __align__(16) float hbuf[2][2][272];
    __shared__ ulonglong2 wsm[8][512];

    const int t     = threadIdx.x;
    const int o     = t >> 1;
    const int half  = t & 1;
    const int myrow = blockIdx.x * 2 + half;

    const float* wrow = Whh + o * HID + half * 128;
    unsigned long long w[48];
#pragma unroll
    for (int q = 0; q < 24; q++) {
        ulonglong2 v = reinterpret_cast<const ulonglong2*>(wrow)[q];
        w[2 * q]     = v.x;
        w[2 * q + 1] = v.y;
    }
#pragma unroll
    for (int j = 0; j < 8; j++)
        wsm[j][t] = reinterpret_cast<const ulonglong2*>(wrow)[24 + j];

    for (int idx = t; idx < 2 * 272; idx += 512)
        (&hbuf[0][0][0])[idx] = 0.0f;
    __syncthreads();

    const float* myxp = xp + (size_t)myrow * SEQ * HID + o;
    __nv_bfloat16* myout = out_seq
        ? out_seq + (size_t)myrow * SEQ * HID + o : (__nv_bfloat16*)0;

    int   buf   = 0;
    float hlast = 0.0f;

    for (int s = 0; s < SEQ; s++) {
        float xv = __ldg(myxp + (size_t)s * HID);

        const ulonglong2* h0 =
            reinterpret_cast<const ulonglong2*>(&hbuf[buf][0][half * 132]);
        const ulonglong2* h1 =
            reinterpret_cast<const ulonglong2*>(&hbuf[buf][1][half * 132]);

        unsigned long long a0 = 0ull, a1 = 0ull;
#pragma unroll
        for (int q = 0; q < 24; q++) {
            ulonglong2 v0 = h0[q], v1 = h1[q];
            a0 = ffma2(w[2 * q],     v0.x, a0);
            a0 = ffma2(w[2 * q + 1], v0.y, a0);
            a1 = ffma2(w[2 * q],     v1.x, a1);
            a1 = ffma2(w[2 * q + 1], v1.y, a1);
        }
#pragma unroll
        for (int j = 0; j < 8; j++) {
            ulonglong2 wv = wsm[j][t];
            ulonglong2 v0 = h0[24 + j], v1 = h1[24 + j];
            a0 = ffma2(wv.x, v0.x, a0);
            a0 = ffma2(wv.y, v0.y, a0);
            a1 = ffma2(wv.x, v1.x, a1);
            a1 = ffma2(wv.y, v1.y, a1);
        }

        float2 f0 = u2f(a0), f1 = u2f(a1);
        float  d0 = f0.x + f0.y;
        float  d1 = f1.x + f1.y;
        d0 += __shfl_xor_sync(0xffffffffu, d0, 1);
        d1 += __shfl_xor_sync(0xffffffffu, d1, 1);

        float hn = tanh_fast((half ? d1 : d0) + xv);
        hlast = hn;

        hbuf[buf ^ 1][half][o + 4 * (o >> 7)] = hn;
        if (myout) myout[(size_t)s * HID] = __float2bfloat16(hn);

        __syncthreads();
        buf ^= 1;
    }

    if (out_final) out_final[(size_t)myrow * HID + o] = hlast;
}

// ---------------------------------------------------------------------------
// Tensor-core GEMM (mma.sync): Y[M,256] = X[M,K] @ W[256,K]^T + bias
// cp.async double-buffered K-chunks of 64.
// USE_ALO=true : 3 passes (Ahi*Bhi + Ahi*Blo + Alo*Bhi)
// USE_ALO=false: 2 passes (Ahi*Bhi + Ahi*Blo), Alo never loaded.
// grid = (M/128, 2).
// ---------------------------------------------------------------------------
#define GSTRIDE 72
#define TILE_B  (128 * GSTRIDE)
#define BUF_B   (4 * TILE_B)
#define GEMM_SMEM (2 * BUF_B * 2 + 128 * 4)

template <int K, bool USE_ALO>
__global__ __launch_bounds__(256) void gemm_mma(
    const __nv_bfloat16* __restrict__ Ahi, const __nv_bfloat16* __restrict__ Alo,
    const __nv_bfloat16* __restrict__ Bhi, const __nv_bfloat16* __restrict__ Blo,
    const float* __restrict__ ba, const float* __restrict__ bb,
    float* __restrict__ Y)
{
    constexpr int NC = K / 64;
    extern __shared__ char smraw[];
    __nv_bfloat16* base = reinterpret_cast<__nv_bfloat16*>(smraw);
    float* bias = reinterpret_cast<float*>(base + 2 * BUF_B);

    const int t      = threadIdx.x;
    const int lane   = t & 31;
    const int wid    = t >> 5;
    const int warp_m = wid >> 1;
    const int warp_n = wid & 1;
    const size_t m0  = (size_t)blockIdx.x * 128;
    const int    n0  = blockIdx.y * 128;

    if (t < 128) bias[t] = ba[n0 + t] + bb[n0 + t];

    float acc[2][8][4];
#pragma unroll
    for (int mt = 0; mt < 2; mt++)
#pragma unroll
        for (int nt = 0; nt < 8; nt++)
#pragma unroll
            for (int i = 0; i < 4; i++) acc[mt][nt][i] = 0.0f;

    const int srow  = t >> 1;
    const int shalf = t & 1;

    const __nv_bfloat16* gA[2] = {Ahi + (m0 + srow) * K + shalf * 32,
                                  Alo + (m0 + srow) * K + shalf * 32};
    const __nv_bfloat16* gB[2] = {Bhi + (size_t)(n0 + srow) * K + shalf * 32,
                                  Blo + (size_t)(n0 + srow) * K + shalf * 32};
    const uint32_t dbase =
        (uint32_t)__cvta_generic_to_shared(base) +
        (uint32_t)((srow * GSTRIDE + shalf * 32) * 2);

    auto issue_chunk = [&](int ci) {
        const uint32_t db = dbase + (uint32_t)((ci & 1) * BUF_B * 2);
        const int koff = ci * 64;
#pragma unroll
        for (int q = 0; q < 4; q++) {
            cp16(db + 0 * TILE_B * 2 + q * 16, gA[0] + koff + q * 8);
            if constexpr (USE_ALO)
                cp16(db + 1 * TILE_B * 2 + q * 16, gA[1] + koff + q * 8);
            cp16(db + 2 * TILE_B * 2 + q * 16, gB[0] + koff + q * 8);
            cp16(db + 3 * TILE_B * 2 + q * 16, gB[1] + koff + q * 8);
        }
        CP_COMMIT();
    };

    issue_chunk(0);
    if (NC > 1) issue_chunk(1);

    for (int ci = 0; ci < NC; ci++) {
        if (ci + 1 < NC) CP_WAIT(1); else CP_WAIT(0);
        __syncthreads();

        const __nv_bfloat16* Ahs = base + (ci & 1) * BUF_B;
        const __nv_bfloat16* Als = Ahs + TILE_B;
        const __nv_bfloat16* Bhs = Als + TILE_B;
        const __nv_bfloat16* Bls = Bhs + TILE_B;

#pragma unroll
        for (int ks = 0; ks < 4; ks++) {
            const int k0 = ks * 16;
            uint32_t ah[2][4], al[2][4];
#pragma unroll
            for (int mt = 0; mt < 2; mt++) {
                int idx = (warp_m * 32 + mt * 16 + (lane >> 2)) * GSTRIDE +
                          k0 + (lane & 3) * 2;
                ah[mt][0] = *reinterpret_cast<const uint32_t*>(&Ahs[idx]);
                ah[mt][1] = *reinterpret_cast<const uint32_t*>(&Ahs[idx + 8 * GSTRIDE]);
                ah[mt][2] = *reinterpret_cast<const uint32_t*>(&Ahs[idx + 8]);
                ah[mt][3] = *reinterpret_cast<const uint32_t*>(&Ahs[idx + 8 * GSTRIDE + 8]);
                if constexpr (USE_ALO) {
                    al[mt][0] = *reinterpret_cast<const uint32_t*>(&Als[idx]);
                    al[mt][1] = *reinterpret_cast<const uint32_t*>(&Als[idx + 8 * GSTRIDE]);
                    al[mt][2] = *reinterpret_cast<const uint32_t*>(&Als[idx + 8]);
                    al[mt][3] = *reinterpret_cast<const uint32_t*>(&Als[idx + 8 * GSTRIDE + 8]);
                }
            }
#pragma unroll
            for (int nt = 0; nt < 8; nt++) {
                int idxb = (warp_n * 64 + nt * 8 + (lane >> 2)) * GSTRIDE +
                           k0 + (lane & 3) * 2;
                uint32_t bh0 = *reinterpret_cast<const uint32_t*>(&Bhs[idxb]);
                uint32_t bh1 = *reinterpret_cast<const uint32_t*>(&Bhs[idxb + 8]);
                uint32_t bl0 = *reinterpret_cast<const uint32_t*>(&Bls[idxb]);
                uint32_t bl1 = *reinterpret_cast<const uint32_t*>(&Bls[idxb + 8]);
#pragma unroll
                for (int mt = 0; mt < 2; mt++) {
                    mma16816(acc[mt][nt], ah[mt], bh0, bh1);   // hi*hi
                    mma16816(acc[mt][nt], ah[mt], bl0, bl1);   // hi*lo
                    if constexpr (USE_ALO)
                        mma16816(acc[mt][nt], al[mt], bh0, bh1);  // lo*hi
                }
            }
        }
        __syncthreads();
        if (ci + 2 < NC) issue_chunk(ci + 2);
    }

#pragma unroll
    for (int mt = 0; mt < 2; mt++) {
        const size_t rbase = m0 + warp_m * 32 + mt * 16 + (lane >> 2);
#pragma unroll
        for (int nt = 0; nt < 8; nt++) {
            const int cl = warp_n * 64 + nt * 8 + (lane & 3) * 2;
            float b0 = bias[cl], b1 = bias[cl + 1];
            float2 v0 = make_float2(acc[mt][nt][0] + b0, acc[mt][nt][1] + b1);
            float2 v1 = make_float2(acc[mt][nt][2] + b0, acc[mt][nt][3] + b1);
            *reinterpret_cast<float2*>(Y + rbase * HID + n0 + cl) = v0;
            *reinterpret_cast<float2*>(Y + (rbase + 8) * HID + n0 + cl) = v1;
        }
    }
}

// ---------------------------------------------------------------------------
// out[b] = sigmoid(h2[b,:] . Wfc + bfc)
// ---------------------------------------------------------------------------
__global__ void fc_sigmoid_kernel(const float* __restrict__ h2,
                                  const float* __restrict__ Wfc,
                                  const float* __restrict__ bfc,
                                  float* __restrict__ out)
{
    __shared__ float wf[HID];
    const int t = threadIdx.x;
    wf[t] = Wfc[t];
    __syncthreads();
    const float* hb = h2 + (size_t)t * HID;
    float s = 0.0f;
#pragma unroll 8
    for (int k = 0; k < HID; k++) s = fmaf(hb[k], wf[k], s);
    float z = s + bfc[0];
    out[t] = 1.0f / (1.0f + expf(-z));
}

// ---------------------------------------------------------------------------
// launch
// ---------------------------------------------------------------------------
extern "C" void kernel_launch(void* const* d_in, const int* in_sizes, int n_in,
                              void* d_out, int out_size)
{
    const float* x     = (const float*)d_in[0];
    const float* W_ih0 = (const float*)d_in[1];
    const float* W_hh0 = (const float*)d_in[2];
    const float* b_ih0 = (const float*)d_in[3];
    const float* b_hh0 = (const float*)d_in[4];
    const float* W_ih1 = (const float*)d_in[5];
    const float* W_hh1 = (const float*)d_in[6];
    const float* b_ih1 = (const float*)d_in[7];
    const float* b_hh1 = (const float*)d_in[8];
    const float* W_fc  = (const float*)d_in[9];
    const float* b_fc  = (const float*)d_in[10];
    float* out = (float*)d_out;

    float *bufA, *hfin;
    __nv_bfloat16 *xhi, *xlo, *hhi, *whi, *wlo;
    cudaGetSymbolAddress((void**)&bufA, g_bufA);
    cudaGetSymbolAddress((void**)&hfin, g_hfin);
    cudaGetSymbolAddress((void**)&xhi, g_xhi);
    cudaGetSymbolAddress((void**)&xlo, g_xlo);
    cudaGetSymbolAddress((void**)&hhi, g_hhi);
    cudaGetSymbolAddress((void**)&whi, g_whi);
    cudaGetSymbolAddress((void**)&wlo, g_wlo);

    cudaFuncSetAttribute(gemm_mma<DIN, true>,
                         cudaFuncAttributeMaxDynamicSharedMemorySize, GEMM_SMEM);
    cudaFuncSetAttribute(gemm_mma<HID, false>,
                         cudaFuncAttributeMaxDynamicSharedMemorySize, GEMM_SMEM);

    const dim3 ggrid(MROWS / 128, 2);

    // ---- phase A: xp0 = x @ W_ih0^T + (b_ih0+b_hh0), bf16x3 ----
    cvt_split_kernel<<<1024, 256>>>(x, xhi, xlo, MROWS * DIN / 4);
    cvt_split_kernel<<<64, 256>>>(W_ih0, whi, wlo, HID * DIN / 4);
    gemm_mma<DIN, true><<<ggrid, 256, GEMM_SMEM>>>(xhi, xlo, whi, wlo,
                                                   b_ih0, b_hh0, bufA);
    // ---- phase B: layer-0 recurrence (fp32 state), emits bf16-hi h1 ----
    rnn_recur_kernel<<<BATCH / 2, 512>>>(bufA, W_hh0, hhi, (float*)0);
    // ---- phase C: xp1 = h1 @ W_ih1^T + (b_ih1+b_hh1), 2-pass ----
    cvt_split_kernel<<<64, 256>>>(W_ih1, whi, wlo, HID * HID / 4);
    gemm_mma<HID, false><<<ggrid, 256, GEMM_SMEM>>>(hhi, hhi, whi, wlo,
                                                    b_ih1, b_hh1, bufA);
    // ---- phase D: layer-1 recurrence -> final h ----
    rnn_recur_kernel<<<BATCH / 2, 512>>>(bufA, W_hh1, (__nv_bfloat16*)0, hfin);
    // ---- phase E: fc + sigmoid ----
    fc_sigmoid_kernel<<<1, HID>>>(hfin, W_fc, b_fc, out);
}